// round 4
// baseline (speedup 1.0000x reference)
#include <cuda_runtime.h>

#define BB    16
#define NN    128
#define FIN   8
#define SDIM  8
#define FO    64
#define KH    32
#define CHUNK 32

// .bss => zero at context init; consumers restore zeros after reading, so
// every call (and every graph replay) starts from zero.
__device__ float g_act [BB * NN * FO];   // [b,n,o] edge contributions
__device__ float g_pool[BB * FO];        // [b,o]   pooled relu sums

// ---------------------------------------------------------------------------
// k_scatter: block = (b,i) source node, 64 threads (t = output channel o).
// ---------------------------------------------------------------------------
__global__ void k_scatter(const float* __restrict__ A,
                          const float* __restrict__ X,
                          const float* __restrict__ E,
                          const float* __restrict__ kn_w1,
                          const float* __restrict__ kn_b1,
                          const float* __restrict__ kn_w2,
                          const float* __restrict__ kn_b2) {
    int bi = blockIdx.x;               // b*N + i
    int b  = bi >> 7;
    int i  = bi & 127;
    int t  = threadIdx.x;              // 0..63

    __shared__ float sw1[SDIM * KH];   // 1KB
    __shared__ float sb1[KH];
    __shared__ float sw2x[KH * FO];    // 8KB
    __shared__ float sh[CHUNK * KH];   // 4KB
    __shared__ float sa[NN];
    __shared__ int   sn[NN];
    __shared__ int   scnt;

    for (int u = t; u < SDIM * KH; u += 64) sw1[u] = kn_w1[u];
    if (t < KH) sb1[t] = kn_b1[t];
    if (t == 0) scnt = 0;
    __syncthreads();

    const float* Ab = A + (size_t)b * NN * NN + i;
#pragma unroll
    for (int r = 0; r < 2; ++r) {
        int n = t + r * 64;
        float a = Ab[n * NN];
        if (a != 0.f) {
            int j = atomicAdd(&scnt, 1);
            sa[j] = a;
            sn[j] = n;
        }
    }

    float xv[FIN];
    const float* x = X + bi * FIN;
#pragma unroll
    for (int f = 0; f < FIN; ++f) xv[f] = x[f];

    const float4* W4 = (const float4*)kn_w2;   // idx = k*128 + f*16 + q
#pragma unroll
    for (int it = 0; it < 8; ++it) {
        int idx = t + 64 * it;
        int k = idx >> 4, q = idx & 15;
        float4 acc = make_float4(0.f, 0.f, 0.f, 0.f);
#pragma unroll
        for (int f = 0; f < FIN; ++f) {
            float4 w = W4[k * 128 + f * 16 + q];
            acc.x = fmaf(w.x, xv[f], acc.x);
            acc.y = fmaf(w.y, xv[f], acc.y);
            acc.z = fmaf(w.z, xv[f], acc.z);
            acc.w = fmaf(w.w, xv[f], acc.w);
        }
        ((float4*)sw2x)[k * 16 + q] = acc;
    }

    float bt = 0.f;
#pragma unroll
    for (int f = 0; f < FIN; ++f) bt = fmaf(kn_b2[f * FO + t], xv[f], bt);

    __syncthreads();
    int cnt = scnt;
    if (cnt == 0) return;

    float w2x[KH];
#pragma unroll
    for (int k = 0; k < KH; ++k) w2x[k] = sw2x[k * FO + t];

    for (int j0 = 0; j0 < cnt; j0 += CHUNK) {
        int m = cnt - j0; if (m > CHUNK) m = CHUNK;

        for (int u = t; u < m * KH; u += 64) {
            int j = u >> 5;
            int k = u & 31;
            const float4* e4 = (const float4*)(E + (((size_t)b * NN + sn[j0 + j]) * NN + i) * SDIM);
            float4 e0 = e4[0], e1 = e4[1];
            float hv = sb1[k];
            hv = fmaf(e0.x, sw1[0 * KH + k], hv);
            hv = fmaf(e0.y, sw1[1 * KH + k], hv);
            hv = fmaf(e0.z, sw1[2 * KH + k], hv);
            hv = fmaf(e0.w, sw1[3 * KH + k], hv);
            hv = fmaf(e1.x, sw1[4 * KH + k], hv);
            hv = fmaf(e1.y, sw1[5 * KH + k], hv);
            hv = fmaf(e1.z, sw1[6 * KH + k], hv);
            hv = fmaf(e1.w, sw1[7 * KH + k], hv);
            sh[u] = fmaxf(hv, 0.f);
        }
        __syncthreads();

        for (int j = 0; j < m; ++j) {
            const float* hj = sh + j * KH;
            float dot = bt;
#pragma unroll
            for (int k = 0; k < KH; ++k) dot = fmaf(hj[k], w2x[k], dot);
            atomicAdd(&g_act[((size_t)b * NN + sn[j0 + j]) * FO + t], sa[j0 + j] * dot);
        }
        __syncthreads();
    }
}

// ---------------------------------------------------------------------------
// k_pool: grid = B*16 blocks, 64 threads. Block (b, c) handles nodes
// [c*8, c*8+8): relu(g_act + root) summed, g_act zero-restored, partial sum
// atomically added into g_pool[b*64+o].
// ---------------------------------------------------------------------------
#define PN 8     // nodes per pool block
__global__ void k_pool(const float* __restrict__ X,
                       const float* __restrict__ root_w,
                       const float* __restrict__ conv_b) {
    int blk = blockIdx.x;              // b*16 + c
    int b   = blk >> 4;
    int c   = blk & 15;
    int o   = threadIdx.x;             // 0..63

    float rw[FIN];
#pragma unroll
    for (int f = 0; f < FIN; ++f) rw[f] = root_w[f * FO + o];
    float cb = conv_b[o];

    int n0 = c * PN;
    float* ga = g_act + ((size_t)b * NN + n0) * FO + o;
    const float* xr0 = X + ((size_t)b * NN + n0) * FIN;

    float s = 0.f;
#pragma unroll
    for (int n = 0; n < PN; ++n) {
        float acc = ga[n * FO];
        ga[n * FO] = 0.f;              // restore zero for next call/replay
        const float* xr = xr0 + n * FIN;
        float rt = cb;
#pragma unroll
        for (int f = 0; f < FIN; ++f) rt = fmaf(xr[f], rw[f], rt);
        s += fmaxf(acc + rt, 0.f);
    }
    atomicAdd(&g_pool[b * FO + o], s);
}

// ---------------------------------------------------------------------------
// k_head: grid = B, 64 threads. Read g_pool (restore zero), Dense(32,relu),
// Dense(1,sigmoid).
// ---------------------------------------------------------------------------
__global__ void k_head(const float* __restrict__ fc_w,
                       const float* __restrict__ fc_b,
                       const float* __restrict__ out_w,
                       const float* __restrict__ out_b,
                       float* __restrict__ out) {
    int b = blockIdx.x;
    int t = threadIdx.x;
    __shared__ float sfeat[FO];

    float v = g_pool[b * FO + t];
    g_pool[b * FO + t] = 0.f;          // restore zero for next call/replay
    sfeat[t] = v * (1.f / NN);
    __syncthreads();

    if (t < 32) {
        float f = fc_b[t];
#pragma unroll
        for (int o2 = 0; o2 < FO; ++o2) f = fmaf(sfeat[o2], fc_w[o2 * 32 + t], f);
        f = fmaxf(f, 0.f);
        float p = f * out_w[t];
#pragma unroll
        for (int off = 16; off > 0; off >>= 1)
            p += __shfl_xor_sync(0xffffffffu, p, off);
        if (t == 0) out[b] = 1.f / (1.f + expf(-(p + out_b[0])));
    }
}

// ---------------------------------------------------------------------------
// Inputs (metadata order): A, X, E, kn_w1, kn_b1, kn_w2, kn_b2, root_w, conv_b,
//                          fc_w, fc_b, out_w, out_b
// ---------------------------------------------------------------------------
extern "C" void kernel_launch(void* const* d_in, const int* in_sizes, int n_in,
                              void* d_out, int out_size) {
    const float* A      = (const float*)d_in[0];
    const float* X      = (const float*)d_in[1];
    const float* E      = (const float*)d_in[2];
    const float* kn_w1  = (const float*)d_in[3];
    const float* kn_b1  = (const float*)d_in[4];
    const float* kn_w2  = (const float*)d_in[5];
    const float* kn_b2  = (const float*)d_in[6];
    const float* root_w = (const float*)d_in[7];
    const float* conv_b = (const float*)d_in[8];
    const float* fc_w   = (const float*)d_in[9];
    const float* fc_b   = (const float*)d_in[10];
    const float* out_w  = (const float*)d_in[11];
    const float* out_b  = (const float*)d_in[12];
    float* out = (float*)d_out;

    k_scatter<<<BB * NN, 64>>>(A, X, E, kn_w1, kn_b1, kn_w2, kn_b2);
    k_pool   <<<BB * 16, 64>>>(X, root_w, conv_b);
    k_head   <<<BB, 64>>>(fc_w, fc_b, out_w, out_b, out);
}

// round 6
// speedup vs baseline: 1.0503x; 1.0503x over previous
#include <cuda_runtime.h>

#define BB    16
#define NN    128
#define FIN   8
#define SDIM  8
#define FO    64
#define KH    32
#define G     4      // sources per scatter block

// .bss => zero at context init; consumers restore zeros after reading, so
// every call (and every graph replay) starts from zero.
__device__ float g_act [BB * NN * FO];   // [b,n,o] edge contributions
__device__ float g_pool[BB * FO];        // [b,o]   pooled relu sums

// ---------------------------------------------------------------------------
// k_scatter: block = G sources (b, i0..i0+G-1), 32*G threads.
// Phase 1 (cooperative): W2x[src][k][o] into smem, each kn_w2 float4 loaded
//   once per block and FMA'd against G X-vectors.
// Phase 2 (warp-per-source, sync-free): lane l owns o=2l,2l+1; h_k in lane k;
//   dot via shuffle broadcast; atomicAdd scatter.
// ---------------------------------------------------------------------------
__global__ void __launch_bounds__(32 * G)
k_scatter(const float* __restrict__ A,
          const float* __restrict__ X,
          const float* __restrict__ E,
          const float* __restrict__ kn_w1,
          const float* __restrict__ kn_b1,
          const float* __restrict__ kn_w2,
          const float* __restrict__ kn_b2) {
    int t    = threadIdx.x;            // 0 .. 32*G-1
    int w    = t >> 5;                 // warp = source slot
    int lane = t & 31;
    int bi0  = blockIdx.x * G;         // G divides NN, so b uniform per block
    int b    = bi0 >> 7;

    __shared__ float sw1 [SDIM * KH];      // 1 KB
    __shared__ float sb1 [KH];
    __shared__ float sxv [G * FIN];        // X rows for the G sources
    __shared__ float sw2x[G * KH * FO];    // 32 KB  w2x[src][k][o]
    __shared__ float s_a [G][NN];          // 2 KB
    __shared__ short s_n [G][NN];          // 1 KB

    for (int u = t; u < SDIM * KH; u += 32 * G) sw1[u] = kn_w1[u];
    if (t < KH)     sb1[t] = kn_b1[t];
    if (t < G * FIN) sxv[t] = X[bi0 * FIN + t];
    __syncthreads();

    // xv for all G sources into registers (uniform across threads)
    float xv[G][FIN];
#pragma unroll
    for (int s = 0; s < G; ++s)
#pragma unroll
        for (int f = 0; f < FIN; ++f) xv[s][f] = sxv[s * FIN + f];

    // Phase 1: cooperative W2x. item idx over (k,q): 32*16 = 512 items.
    const float4* W4 = (const float4*)kn_w2;          // idx = k*128 + f*16 + q
#pragma unroll
    for (int it = 0; it < 512 / (32 * G); ++it) {
        int idx = t + 32 * G * it;
        int k = idx >> 4, q = idx & 15;
        float4 wv[FIN];
#pragma unroll
        for (int f = 0; f < FIN; ++f) wv[f] = W4[k * 128 + f * 16 + q];
#pragma unroll
        for (int s = 0; s < G; ++s) {
            float4 acc = make_float4(0.f, 0.f, 0.f, 0.f);
#pragma unroll
            for (int f = 0; f < FIN; ++f) {
                acc.x = fmaf(wv[f].x, xv[s][f], acc.x);
                acc.y = fmaf(wv[f].y, xv[s][f], acc.y);
                acc.z = fmaf(wv[f].z, xv[s][f], acc.z);
                acc.w = fmaf(wv[f].w, xv[s][f], acc.w);
            }
            ((float4*)sw2x)[s * (KH * 16) + k * 16 + q] = acc;
        }
    }
    __syncthreads();

    // ---- Phase 2: warp w owns source i = (bi0&127) + w ----
    int i = (bi0 & 127) + w;

    // nnz compaction of column A[b, :, i] via ballot
    const float* Ab = A + (size_t)b * NN * NN + i;
    int cnt = 0;
#pragma unroll
    for (int c = 0; c < NN / 32; ++c) {
        int n = c * 32 + lane;
        float a = Ab[n * NN];
        unsigned m = __ballot_sync(0xffffffffu, a != 0.f);
        if (a != 0.f) {
            int pos = cnt + __popc(m & ((1u << lane) - 1u));
            s_a[w][pos] = a;
            s_n[w][pos] = (short)n;
        }
        cnt += __popc(m);
    }
    __syncwarp();   // order s_a/s_n writes before cross-lane reads below

    // w2x for o=2*lane, 2*lane+1 into registers
    float w2a[KH], w2b[KH];
#pragma unroll
    for (int k = 0; k < KH; ++k) {
        float2 v = ((const float2*)(sw2x + (w * KH + k) * FO))[lane];
        w2a[k] = v.x; w2b[k] = v.y;
    }
    // bt for the two channels
    float bta = 0.f, btb = 0.f;
    {
        const float2* B2 = (const float2*)kn_b2;
#pragma unroll
        for (int f = 0; f < FIN; ++f) {
            float2 v = B2[f * (FO / 2) + lane];
            bta = fmaf(v.x, sxv[w * FIN + f], bta);
            btb = fmaf(v.y, sxv[w * FIN + f], btb);
        }
    }

    const float* Eb = E + ((size_t)b * NN * NN + i) * SDIM;   // + n*NN*SDIM
    float* ga = g_act + (size_t)b * NN * FO;

    for (int j = 0; j < cnt; ++j) {
        int   n = s_n[w][j];
        float a = s_a[w][j];

        // h_k for k = lane
        const float4* e4 = (const float4*)(Eb + (size_t)n * NN * SDIM);
        float4 e0 = e4[0], e1 = e4[1];
        float hv = sb1[lane];
        hv = fmaf(e0.x, sw1[0 * KH + lane], hv);
        hv = fmaf(e0.y, sw1[1 * KH + lane], hv);
        hv = fmaf(e0.z, sw1[2 * KH + lane], hv);
        hv = fmaf(e0.w, sw1[3 * KH + lane], hv);
        hv = fmaf(e1.x, sw1[4 * KH + lane], hv);
        hv = fmaf(e1.y, sw1[5 * KH + lane], hv);
        hv = fmaf(e1.z, sw1[6 * KH + lane], hv);
        hv = fmaf(e1.w, sw1[7 * KH + lane], hv);
        hv = fmaxf(hv, 0.f);

        // dot over k via shuffle broadcast; even/odd split halves the chain
        float da0 = bta, db0 = btb, da1 = 0.f, db1 = 0.f;
#pragma unroll
        for (int k = 0; k < KH; k += 2) {
            float h0 = __shfl_sync(0xffffffffu, hv, k);
            float h1 = __shfl_sync(0xffffffffu, hv, k + 1);
            da0 = fmaf(h0, w2a[k],     da0);
            db0 = fmaf(h0, w2b[k],     db0);
            da1 = fmaf(h1, w2a[k + 1], da1);
            db1 = fmaf(h1, w2b[k + 1], db1);
        }
        float da = (da0 + da1) * a;
        float db = (db0 + db1) * a;

        float* dst = ga + n * FO + 2 * lane;
        atomicAdd(dst,     da);
        atomicAdd(dst + 1, db);
    }
}

// ---------------------------------------------------------------------------
// k_pool: grid = B*16 blocks, 64 threads. Block (b,c) handles 8 nodes:
// relu(g_act + root) summed, g_act zero-restored, partial into g_pool.
// ---------------------------------------------------------------------------
#define PN 8
__global__ void k_pool(const float* __restrict__ X,
                       const float* __restrict__ root_w,
                       const float* __restrict__ conv_b) {
    int blk = blockIdx.x;              // b*16 + c
    int b   = blk >> 4;
    int c   = blk & 15;
    int o   = threadIdx.x;             // 0..63

    float rw[FIN];
#pragma unroll
    for (int f = 0; f < FIN; ++f) rw[f] = root_w[f * FO + o];
    float cb = conv_b[o];

    int n0 = c * PN;
    float* ga = g_act + ((size_t)b * NN + n0) * FO + o;
    const float* xr0 = X + ((size_t)b * NN + n0) * FIN;

    float s = 0.f;
#pragma unroll
    for (int n = 0; n < PN; ++n) {
        float acc = ga[n * FO];
        ga[n * FO] = 0.f;              // restore zero for next call/replay
        const float* xr = xr0 + n * FIN;
        float rt = cb;
#pragma unroll
        for (int f = 0; f < FIN; ++f) rt = fmaf(xr[f], rw[f], rt);
        s += fmaxf(acc + rt, 0.f);
    }
    atomicAdd(&g_pool[b * FO + o], s);
}

// ---------------------------------------------------------------------------
// k_head: grid = B, 64 threads. Read g_pool (restore zero), Dense(32,relu),
// Dense(1,sigmoid).
// ---------------------------------------------------------------------------
__global__ void k_head(const float* __restrict__ fc_w,
                       const float* __restrict__ fc_b,
                       const float* __restrict__ out_w,
                       const float* __restrict__ out_b,
                       float* __restrict__ out) {
    int b = blockIdx.x;
    int t = threadIdx.x;
    __shared__ float sfeat[FO];

    float v = g_pool[b * FO + t];
    g_pool[b * FO + t] = 0.f;          // restore zero for next call/replay
    sfeat[t] = v * (1.f / NN);
    __syncthreads();

    if (t < 32) {
        float f = fc_b[t];
#pragma unroll
        for (int o2 = 0; o2 < FO; ++o2) f = fmaf(sfeat[o2], fc_w[o2 * 32 + t], f);
        f = fmaxf(f, 0.f);
        float p = f * out_w[t];
#pragma unroll
        for (int off = 16; off > 0; off >>= 1)
            p += __shfl_xor_sync(0xffffffffu, p, off);
        if (t == 0) out[b] = 1.f / (1.f + expf(-(p + out_b[0])));
    }
}

// ---------------------------------------------------------------------------
// Inputs (metadata order): A, X, E, kn_w1, kn_b1, kn_w2, kn_b2, root_w, conv_b,
//                          fc_w, fc_b, out_w, out_b
// ---------------------------------------------------------------------------
extern "C" void kernel_launch(void* const* d_in, const int* in_sizes, int n_in,
                              void* d_out, int out_size) {
    const float* A      = (const float*)d_in[0];
    const float* X      = (const float*)d_in[1];
    const float* E      = (const float*)d_in[2];
    const float* kn_w1  = (const float*)d_in[3];
    const float* kn_b1  = (const float*)d_in[4];
    const float* kn_w2  = (const float*)d_in[5];
    const float* kn_b2  = (const float*)d_in[6];
    const float* root_w = (const float*)d_in[7];
    const float* conv_b = (const float*)d_in[8];
    const float* fc_w   = (const float*)d_in[9];
    const float* fc_b   = (const float*)d_in[10];
    const float* out_w  = (const float*)d_in[11];
    const float* out_b  = (const float*)d_in[12];
    float* out = (float*)d_out;

    k_scatter<<<(BB * NN) / G, 32 * G>>>(A, X, E, kn_w1, kn_b1, kn_w2, kn_b2);
    k_pool   <<<BB * 16, 64>>>(X, root_w, conv_b);
    k_head   <<<BB, 64>>>(fc_w, fc_b, out_w, out_b, out);
}

// round 9
// speedup vs baseline: 1.0918x; 1.0395x over previous
#include <cuda_runtime.h>

#define BB    16
#define NN    128
#define FIN   8
#define SDIM  8
#define FO    64
#define KH    32
#define G     4      // sources per scatter block
#define NT    256    // threads per scatter block (2 warps per source)

// .bss => zero at context init; consumers restore zeros after reading, so
// every call (and every graph replay) starts from zero.
__device__ float g_act [BB * NN * FO];   // [b,n,o] edge contributions
__device__ float g_pool[BB * FO];        // [b,o]   pooled relu sums

// ---------------------------------------------------------------------------
// k_scatter: block = G sources, 256 threads = 8 warps, 2 warps per source
// (split edge list by parity). lane l owns o=2l,2l+1; h_k in lane k; dot via
// shuffle broadcast; atomicAdd scatter.
// ---------------------------------------------------------------------------
__global__ void __launch_bounds__(NT)
k_scatter(const float* __restrict__ A,
          const float* __restrict__ X,
          const float* __restrict__ E,
          const float* __restrict__ kn_w1,
          const float* __restrict__ kn_b1,
          const float* __restrict__ kn_w2,
          const float* __restrict__ kn_b2) {
    int t    = threadIdx.x;            // 0..255
    int w    = t >> 5;                 // warp 0..7
    int lane = t & 31;
    int src  = w & 3;                  // source slot 0..3
    int half = w >> 2;                 // edge parity 0/1
    int bi0  = blockIdx.x * G;
    int b    = bi0 >> 7;

    __shared__ float sw1 [SDIM * KH];      // 1 KB
    __shared__ float sb1 [KH];
    __shared__ float sxv [G * FIN];
    __shared__ float sw2x[G * KH * FO];    // 32 KB  w2x[src][k][o]
    __shared__ float s_a [G][NN];          // 2 KB
    __shared__ short s_n [G][NN];          // 1 KB
    __shared__ int   s_cnt[G];

    if (t < SDIM * KH) sw1[t] = kn_w1[t];          // 256 threads cover all 256
    if (t < KH)        sb1[t] = kn_b1[t];          // FIXED: reachable guard
    if (t < G * FIN)   sxv[t] = X[bi0 * FIN + t];
    __syncthreads();

    float xv[G][FIN];
#pragma unroll
    for (int s = 0; s < G; ++s)
#pragma unroll
        for (int f = 0; f < FIN; ++f) xv[s][f] = sxv[s * FIN + f];

    // Phase 1: cooperative W2x. 512 (k,q) items over 256 threads.
    const float4* W4 = (const float4*)kn_w2;          // idx = k*128 + f*16 + q
#pragma unroll
    for (int it = 0; it < 512 / NT; ++it) {
        int idx = t + NT * it;
        int k = idx >> 4, q = idx & 15;
        float4 wv[FIN];
#pragma unroll
        for (int f = 0; f < FIN; ++f) wv[f] = W4[k * 128 + f * 16 + q];
#pragma unroll
        for (int s = 0; s < G; ++s) {
            float4 acc = make_float4(0.f, 0.f, 0.f, 0.f);
#pragma unroll
            for (int f = 0; f < FIN; ++f) {
                acc.x = fmaf(wv[f].x, xv[s][f], acc.x);
                acc.y = fmaf(wv[f].y, xv[s][f], acc.y);
                acc.z = fmaf(wv[f].z, xv[s][f], acc.z);
                acc.w = fmaf(wv[f].w, xv[s][f], acc.w);
            }
            ((float4*)sw2x)[s * (KH * 16) + k * 16 + q] = acc;
        }
    }

    int i = (bi0 & 127) + src;

    // nnz compaction of column A[b,:,i] by the half==0 warp of each source
    if (half == 0) {
        const float* Ab = A + (size_t)b * NN * NN + i;
        int cnt = 0;
#pragma unroll
        for (int c = 0; c < NN / 32; ++c) {
            int n = c * 32 + lane;
            float a = Ab[n * NN];
            unsigned m = __ballot_sync(0xffffffffu, a != 0.f);
            if (a != 0.f) {
                int pos = cnt + __popc(m & ((1u << lane) - 1u));
                s_a[src][pos] = a;
                s_n[src][pos] = (short)n;
            }
            cnt += __popc(m);
        }
        if (lane == 0) s_cnt[src] = cnt;
    }

    // bt for channels o = 2*lane, 2*lane+1
    float bta = 0.f, btb = 0.f;
    {
        const float2* B2 = (const float2*)kn_b2;
#pragma unroll
        for (int f = 0; f < FIN; ++f) {
            float2 v = B2[f * (FO / 2) + lane];
            bta = fmaf(v.x, xv[src][f], bta);
            btb = fmaf(v.y, xv[src][f], btb);
        }
    }
    __syncthreads();   // sw2x + edge lists visible to all 8 warps

    // w2x for this source, channels 2*lane, 2*lane+1
    float w2a[KH], w2b[KH];
#pragma unroll
    for (int k = 0; k < KH; ++k) {
        float2 v = ((const float2*)(sw2x + (src * KH + k) * FO))[lane];
        w2a[k] = v.x; w2b[k] = v.y;
    }

    int cnt = s_cnt[src];
    const float* Eb = E + ((size_t)b * NN * NN + i) * SDIM;
    float* ga = g_act + (size_t)b * NN * FO;

    // software-pipelined edge loop: this warp takes j = half, half+2, ...
    int j = half;
    if (j < cnt) {
        const float4* e4 = (const float4*)(Eb + (size_t)s_n[src][j] * NN * SDIM);
        float4 e0 = e4[0], e1 = e4[1];

        for (; j < cnt; j += 2) {
            int   n = s_n[src][j];
            float a = s_a[src][j];

            // prefetch next edge's E row
            float4 p0, p1;
            int jn = j + 2;
            if (jn < cnt) {
                const float4* pe = (const float4*)(Eb + (size_t)s_n[src][jn] * NN * SDIM);
                p0 = pe[0]; p1 = pe[1];
            }

            // h_k for k = lane
            float hv = sb1[lane];
            hv = fmaf(e0.x, sw1[0 * KH + lane], hv);
            hv = fmaf(e0.y, sw1[1 * KH + lane], hv);
            hv = fmaf(e0.z, sw1[2 * KH + lane], hv);
            hv = fmaf(e0.w, sw1[3 * KH + lane], hv);
            hv = fmaf(e1.x, sw1[4 * KH + lane], hv);
            hv = fmaf(e1.y, sw1[5 * KH + lane], hv);
            hv = fmaf(e1.z, sw1[6 * KH + lane], hv);
            hv = fmaf(e1.w, sw1[7 * KH + lane], hv);
            hv = fmaxf(hv, 0.f);

            // dot over k via shuffle broadcast; 4 independent chains
            float da0 = bta, db0 = btb, da1 = 0.f, db1 = 0.f;
#pragma unroll
            for (int k = 0; k < KH; k += 2) {
                float h0 = __shfl_sync(0xffffffffu, hv, k);
                float h1 = __shfl_sync(0xffffffffu, hv, k + 1);
                da0 = fmaf(h0, w2a[k],     da0);
                db0 = fmaf(h0, w2b[k],     db0);
                da1 = fmaf(h1, w2a[k + 1], da1);
                db1 = fmaf(h1, w2b[k + 1], db1);
            }
            float da = (da0 + da1) * a;
            float db = (db0 + db1) * a;

            float* dst = ga + n * FO + 2 * lane;
            atomicAdd(dst,     da);
            atomicAdd(dst + 1, db);

            e0 = p0; e1 = p1;
        }
    }
}

// ---------------------------------------------------------------------------
// k_pool: grid = B*32 blocks, 64 threads. Block (b,c) handles 4 nodes:
// relu(g_act + root) summed, g_act zero-restored, partial into g_pool.
// ---------------------------------------------------------------------------
#define PN 4
__global__ void k_pool(const float* __restrict__ X,
                       const float* __restrict__ root_w,
                       const float* __restrict__ conv_b) {
    int blk = blockIdx.x;              // b*32 + c
    int b   = blk >> 5;
    int c   = blk & 31;
    int o   = threadIdx.x;             // 0..63

    float rw[FIN];
#pragma unroll
    for (int f = 0; f < FIN; ++f) rw[f] = root_w[f * FO + o];
    float cb = conv_b[o];

    int n0 = c * PN;
    float* ga = g_act + ((size_t)b * NN + n0) * FO + o;
    const float* xr0 = X + ((size_t)b * NN + n0) * FIN;

    float s = 0.f;
#pragma unroll
    for (int n = 0; n < PN; ++n) {
        float acc = ga[n * FO];
        ga[n * FO] = 0.f;              // restore zero for next call/replay
        const float* xr = xr0 + n * FIN;
        float rt = cb;
#pragma unroll
        for (int f = 0; f < FIN; ++f) rt = fmaf(xr[f], rw[f], rt);
        s += fmaxf(acc + rt, 0.f);
    }
    atomicAdd(&g_pool[b * FO + o], s);
}

// ---------------------------------------------------------------------------
// k_head: grid = B, 64 threads. Read g_pool (restore zero), Dense(32,relu),
// Dense(1,sigmoid).
// ---------------------------------------------------------------------------
__global__ void k_head(const float* __restrict__ fc_w,
                       const float* __restrict__ fc_b,
                       const float* __restrict__ out_w,
                       const float* __restrict__ out_b,
                       float* __restrict__ out) {
    int b = blockIdx.x;
    int t = threadIdx.x;
    __shared__ float sfeat[FO];

    float v = g_pool[b * FO + t];
    g_pool[b * FO + t] = 0.f;          // restore zero for next call/replay
    sfeat[t] = v * (1.f / NN);
    __syncthreads();

    if (t < 32) {
        float f = fc_b[t];
#pragma unroll
        for (int o2 = 0; o2 < FO; ++o2) f = fmaf(sfeat[o2], fc_w[o2 * 32 + t], f);
        f = fmaxf(f, 0.f);
        float p = f * out_w[t];
#pragma unroll
        for (int off = 16; off > 0; off >>= 1)
            p += __shfl_xor_sync(0xffffffffu, p, off);
        if (t == 0) out[b] = 1.f / (1.f + expf(-(p + out_b[0])));
    }
}

// ---------------------------------------------------------------------------
// Inputs (metadata order): A, X, E, kn_w1, kn_b1, kn_w2, kn_b2, root_w, conv_b,
//                          fc_w, fc_b, out_w, out_b
// ---------------------------------------------------------------------------
extern "C" void kernel_launch(void* const* d_in, const int* in_sizes, int n_in,
                              void* d_out, int out_size) {
    const float* A      = (const float*)d_in[0];
    const float* X      = (const float*)d_in[1];
    const float* E      = (const float*)d_in[2];
    const float* kn_w1  = (const float*)d_in[3];
    const float* kn_b1  = (const float*)d_in[4];
    const float* kn_w2  = (const float*)d_in[5];
    const float* kn_b2  = (const float*)d_in[6];
    const float* root_w = (const float*)d_in[7];
    const float* conv_b = (const float*)d_in[8];
    const float* fc_w   = (const float*)d_in[9];
    const float* fc_b   = (const float*)d_in[10];
    const float* out_w  = (const float*)d_in[11];
    const float* out_b  = (const float*)d_in[12];
    float* out = (float*)d_out;

    k_scatter<<<(BB * NN) / G, NT>>>(A, X, E, kn_w1, kn_b1, kn_w2, kn_b2);
    k_pool   <<<BB * 32, 64>>>(X, root_w, conv_b);
    k_head   <<<BB, 64>>>(fc_w, fc_b, out_w, out_b, out);
}

// round 10
// speedup vs baseline: 1.4484x; 1.3266x over previous
#include <cuda_runtime.h>

#define BB    16
#define NN    128
#define FIN   8
#define SDIM  8
#define FO    64
#define KH    32
#define VROW  288          // padded V row stride in floats (272 used)
#define CAP   64           // max edges per destination (nnz ~13, P(>64) ~ 0)

// g_V fully overwritten each call (no zero-restore needed).
// g_pool accumulated by k_gemm, zero-restored by k_head (replay-safe).
__device__ float g_V   [BB * NN * VROW];   // [bn][ P(256) | Q(8) | x(8) | pad ]
__device__ float g_pool[BB * FO];

// ---------------------------------------------------------------------------
// k_build: grid 512, block 256 = 8 warps: 4 destinations x 2 warps (edge parity).
// Lane l owns k=l: h_l computed locally, P[l][f] (8 regs) accumulated, no shuffles.
// ---------------------------------------------------------------------------
__global__ void __launch_bounds__(256)
k_build(const float* __restrict__ A,
        const float* __restrict__ X,
        const float* __restrict__ E,
        const float* __restrict__ kn_w1,
        const float* __restrict__ kn_b1) {
    int t    = threadIdx.x;        // 0..255
    int w    = t >> 5;             // warp 0..7
    int lane = t & 31;
    int d    = w >> 1;             // destination slot 0..3
    int pr   = w & 1;              // edge parity
    int b    = blockIdx.x >> 5;    // 32 blocks per b
    int n0   = (blockIdx.x & 31) * 4;
    int n    = n0 + d;

    __shared__ float sw1 [SDIM * KH];   // 1KB, [s][k]
    __shared__ float sb1 [KH];
    __shared__ float sxb [NN * FIN];    // 4KB, X[b]
    __shared__ float sa  [4][CAP];
    __shared__ short sn  [4][CAP];
    __shared__ int   scnt[4];
    __shared__ float sP  [4][2][264];   // P(256)+Q(8) per (dest, parity)

    sw1[t] = kn_w1[t];                                  // 256 threads == 256 elems
    if (t < KH) sb1[t] = kn_b1[t];                      // threads 0..31
    ((float4*)sxb)[t] = ((const float4*)(X + (size_t)b * NN * FIN))[t];  // 256 float4

    // parity-0 warp of each dest compacts row A[b,n,:] (contiguous)
    if (pr == 0) {
        const float4* Ar = (const float4*)(A + ((size_t)b * NN + n) * NN);
        float4 av = Ar[lane];                           // i = 4*lane .. +3
        int cnt = 0;
#pragma unroll
        for (int e = 0; e < 4; ++e) {
            float v = (e == 0) ? av.x : (e == 1) ? av.y : (e == 2) ? av.z : av.w;
            unsigned m = __ballot_sync(0xffffffffu, v != 0.f);
            if (v != 0.f) {
                int pos = cnt + __popc(m & ((1u << lane) - 1u));
                if (pos < CAP) { sa[d][pos] = v; sn[d][pos] = (short)(4 * lane + e); }
            }
            cnt += __popc(m);
        }
        if (lane == 0) scnt[d] = (cnt > CAP) ? CAP : cnt;
    }
    __syncthreads();

    int cnt = scnt[d];
    float P[8] = {0.f, 0.f, 0.f, 0.f, 0.f, 0.f, 0.f, 0.f};
    float q[8] = {0.f, 0.f, 0.f, 0.f, 0.f, 0.f, 0.f, 0.f};
    const float* Erow = E + ((size_t)b * NN + n) * NN * SDIM;

    int j = pr;
    if (j < cnt) {
        int   i = sn[d][j];
        float a = sa[d][j];
        const float4* e4 = (const float4*)(Erow + (size_t)i * SDIM);
        float4 e0 = e4[0], e1 = e4[1];

        while (j < cnt) {
            int jn = j + 2;
            int inext = 0; float anext = 0.f;
            float4 p0 = e0, p1 = e1;
            if (jn < cnt) {
                inext = sn[d][jn]; anext = sa[d][jn];
                const float4* pe = (const float4*)(Erow + (size_t)inext * SDIM);
                p0 = pe[0]; p1 = pe[1];
            }

            // h_k for k = lane
            float hv = sb1[lane];
            hv = fmaf(e0.x, sw1[0 * KH + lane], hv);
            hv = fmaf(e0.y, sw1[1 * KH + lane], hv);
            hv = fmaf(e0.z, sw1[2 * KH + lane], hv);
            hv = fmaf(e0.w, sw1[3 * KH + lane], hv);
            hv = fmaf(e1.x, sw1[4 * KH + lane], hv);
            hv = fmaf(e1.y, sw1[5 * KH + lane], hv);
            hv = fmaf(e1.z, sw1[6 * KH + lane], hv);
            hv = fmaf(e1.w, sw1[7 * KH + lane], hv);
            hv = fmaxf(hv, 0.f);
            float ah = a * hv;

            const float4* xp = (const float4*)(sxb + i * FIN);  // broadcast LDS
            float4 x0 = xp[0], x1 = xp[1];
            P[0] = fmaf(ah, x0.x, P[0]);  P[1] = fmaf(ah, x0.y, P[1]);
            P[2] = fmaf(ah, x0.z, P[2]);  P[3] = fmaf(ah, x0.w, P[3]);
            P[4] = fmaf(ah, x1.x, P[4]);  P[5] = fmaf(ah, x1.y, P[5]);
            P[6] = fmaf(ah, x1.z, P[6]);  P[7] = fmaf(ah, x1.w, P[7]);
            q[0] = fmaf(a, x0.x, q[0]);   q[1] = fmaf(a, x0.y, q[1]);
            q[2] = fmaf(a, x0.z, q[2]);   q[3] = fmaf(a, x0.w, q[3]);
            q[4] = fmaf(a, x1.x, q[4]);   q[5] = fmaf(a, x1.y, q[5]);
            q[6] = fmaf(a, x1.z, q[6]);   q[7] = fmaf(a, x1.w, q[7]);

            j = jn; i = inext; a = anext; e0 = p0; e1 = p1;
        }
    }

    // stage per-parity partials
    {
        float* dst = sP[d][pr];
        float4 pa = make_float4(P[0], P[1], P[2], P[3]);
        float4 pb = make_float4(P[4], P[5], P[6], P[7]);
        ((float4*)(dst + lane * 8))[0] = pa;
        ((float4*)(dst + lane * 8))[1] = pb;
        if (lane == 0) {
#pragma unroll
            for (int f = 0; f < 8; ++f) dst[256 + f] = q[f];
        }
    }
    __syncthreads();

    // merge parities and write V row
    if (w < 4) {
        int d2 = w, n2 = n0 + d2;
        float* vrow = g_V + ((size_t)b * NN + n2) * VROW;
        const float* pA = sP[d2][0];
        const float* pB = sP[d2][1];
        float4 a0 = ((const float4*)(pA + lane * 8))[0];
        float4 a1 = ((const float4*)(pA + lane * 8))[1];
        float4 b0 = ((const float4*)(pB + lane * 8))[0];
        float4 b1 = ((const float4*)(pB + lane * 8))[1];
        a0.x += b0.x; a0.y += b0.y; a0.z += b0.z; a0.w += b0.w;
        a1.x += b1.x; a1.y += b1.y; a1.z += b1.z; a1.w += b1.w;
        ((float4*)(vrow + lane * 8))[0] = a0;
        ((float4*)(vrow + lane * 8))[1] = a1;
        if (lane < 8) {
            vrow[256 + lane] = pA[256 + lane] + pB[256 + lane];   // Q
            vrow[264 + lane] = sxb[n2 * FIN + lane];              // x
        }
    }
}

// ---------------------------------------------------------------------------
// k_gemm: grid 256 (b, 8-dest group), block 256.
// Thread (og = t&15 -> o-quad, jq = t>>4 -> 17-row j slice) holds its W slice
// (17 x float4) in registers and loops the 8 destinations. Fuses conv_b + ReLU
// + pool into g_pool.
// ---------------------------------------------------------------------------
__global__ void __launch_bounds__(256)
k_gemm(const float* __restrict__ kn_w2,
       const float* __restrict__ kn_b2,
       const float* __restrict__ root_w,
       const float* __restrict__ conv_b) {
    int t    = threadIdx.x;
    int w    = t >> 5;             // warp 0..7
    int lane = t & 31;
    int og   = t & 15;             // o = og*4 .. +4
    int jbase = (t >> 4) * 17;     // jq 0..15 -> j slice [jbase, jbase+17)
    int b    = blockIdx.x >> 4;
    int n0   = (blockIdx.x & 15) * 8;

    __shared__ float sV    [8][VROW];   // 9KB
    __shared__ float s_part[8][FO];     // 2KB

    // warp w loads V row for dest w (272 floats = 68 float4)
    {
        const float4* src = (const float4*)(g_V + ((size_t)b * NN + n0 + w) * VROW);
        for (int u = lane; u < 68; u += 32) ((float4*)sV[w])[u] = src[u];
    }

    // W slice into registers: rows j = jbase..jbase+16, columns og*4..+4
    float4 Wr[17];
#pragma unroll
    for (int jj = 0; jj < 17; ++jj) {
        int jg = jbase + jj;
        const float* src;
        if (jg < 256)      src = kn_w2  + jg * 64;
        else if (jg < 264) src = kn_b2  + (jg - 256) * 64;
        else               src = root_w + (jg - 264) * 64;
        Wr[jj] = ((const float4*)src)[og];
    }
    __syncthreads();

    float cb = (t < FO) ? conv_b[t] : 0.f;
    float pool = 0.f;

    for (int d = 0; d < 8; ++d) {
        float4 acc = make_float4(0.f, 0.f, 0.f, 0.f);
        const float* V = sV[d] + jbase;
#pragma unroll
        for (int jj = 0; jj < 17; ++jj) {
            float vj = V[jj];
            acc.x = fmaf(Wr[jj].x, vj, acc.x);
            acc.y = fmaf(Wr[jj].y, vj, acc.y);
            acc.z = fmaf(Wr[jj].z, vj, acc.z);
            acc.w = fmaf(Wr[jj].w, vj, acc.w);
        }
        // combine the two jq slices within this warp (lanes l and l^16)
        acc.x += __shfl_xor_sync(0xffffffffu, acc.x, 16);
        acc.y += __shfl_xor_sync(0xffffffffu, acc.y, 16);
        acc.z += __shfl_xor_sync(0xffffffffu, acc.z, 16);
        acc.w += __shfl_xor_sync(0xffffffffu, acc.w, 16);
        if (lane < 16) ((float4*)s_part[w])[og] = acc;
        __syncthreads();
        if (t < FO) {
            float s = 0.f;
#pragma unroll
            for (int ww = 0; ww < 8; ++ww) s += s_part[ww][t];
            pool += fmaxf(s + cb, 0.f);
        }
        __syncthreads();
    }

    if (t < FO) atomicAdd(&g_pool[b * FO + t], pool);
}

// ---------------------------------------------------------------------------
// k_head: grid B, 64 threads. Read g_pool (restore zero), /N, Dense(32,relu),
// Dense(1,sigmoid).
// ---------------------------------------------------------------------------
__global__ void k_head(const float* __restrict__ fc_w,
                       const float* __restrict__ fc_b,
                       const float* __restrict__ out_w,
                       const float* __restrict__ out_b,
                       float* __restrict__ out) {
    int b = blockIdx.x;
    int t = threadIdx.x;
    __shared__ float sfeat[FO];

    float v = g_pool[b * FO + t];
    g_pool[b * FO + t] = 0.f;          // restore zero for next call/replay
    sfeat[t] = v * (1.f / NN);
    __syncthreads();

    if (t < 32) {
        float f = fc_b[t];
#pragma unroll
        for (int o2 = 0; o2 < FO; ++o2) f = fmaf(sfeat[o2], fc_w[o2 * 32 + t], f);
        f = fmaxf(f, 0.f);
        float p = f * out_w[t];
#pragma unroll
        for (int off = 16; off > 0; off >>= 1)
            p += __shfl_xor_sync(0xffffffffu, p, off);
        if (t == 0) out[b] = 1.f / (1.f + expf(-(p + out_b[0])));
    }
}

// ---------------------------------------------------------------------------
// Inputs (metadata order): A, X, E, kn_w1, kn_b1, kn_w2, kn_b2, root_w, conv_b,
//                          fc_w, fc_b, out_w, out_b
// ---------------------------------------------------------------------------
extern "C" void kernel_launch(void* const* d_in, const int* in_sizes, int n_in,
                              void* d_out, int out_size) {
    const float* A      = (const float*)d_in[0];
    const float* X      = (const float*)d_in[1];
    const float* E      = (const float*)d_in[2];
    const float* kn_w1  = (const float*)d_in[3];
    const float* kn_b1  = (const float*)d_in[4];
    const float* kn_w2  = (const float*)d_in[5];
    const float* kn_b2  = (const float*)d_in[6];
    const float* root_w = (const float*)d_in[7];
    const float* conv_b = (const float*)d_in[8];
    const float* fc_w   = (const float*)d_in[9];
    const float* fc_b   = (const float*)d_in[10];
    const float* out_w  = (const float*)d_in[11];
    const float* out_b  = (const float*)d_in[12];
    float* out = (float*)d_out;

    k_build<<<512, 256>>>(A, X, E, kn_w1, kn_b1);
    k_gemm <<<256, 256>>>(kn_w2, kn_b2, root_w, conv_b);
    k_head <<<BB, 64>>>(fc_w, fc_b, out_w, out_b, out);
}

// round 16
// speedup vs baseline: 1.4784x; 1.0207x over previous
#include <cuda_runtime.h>

#define BB    16
#define NN    128
#define FIN   8
#define SDIM  8
#define FO    64
#define KH    32
#define VROW  288          // padded V row stride in floats (272 used)
#define CAP   64           // max edges per destination (nnz ~13)

// g_V fully overwritten each call (no zero-restore needed).
// g_pool accumulated by k_gemm, zero-restored by k_head (replay-safe).
__device__ float g_V   [BB * NN * VROW];   // [bn][ P(256) | Q(8) | x(8) | pad ]
__device__ float g_pool[BB * FO];

// ---------------------------------------------------------------------------
// k_build: grid 1024, block 128 = 4 warps: 2 destinations x 2 warps (parity).
// Lane l owns k=l: h_l computed locally, P[l][f] (8 regs) accumulated.
// ---------------------------------------------------------------------------
__global__ void __launch_bounds__(128)
k_build(const float* __restrict__ A,
        const float* __restrict__ X,
        const float* __restrict__ E,
        const float* __restrict__ kn_w1,
        const float* __restrict__ kn_b1) {
    int t    = threadIdx.x;        // 0..127
    int w    = t >> 5;             // warp 0..3
    int lane = t & 31;
    int d    = w >> 1;             // destination slot 0..1
    int pr   = w & 1;              // edge parity
    int b    = blockIdx.x >> 6;    // 64 blocks per b
    int n0   = (blockIdx.x & 63) * 2;
    int n    = n0 + d;

    __shared__ alignas(16) float sw1 [SDIM * KH];   // 1KB, [s][k]
    __shared__ alignas(16) float sb1 [KH];
    __shared__ alignas(16) float sxb [NN * FIN];    // 4KB, X[b]
    __shared__ alignas(16) float sa  [2][CAP];
    __shared__ alignas(16) short sn  [2][CAP];
    __shared__ alignas(16) int   scnt[4];           // padded to 16B
    __shared__ alignas(16) float sP  [2][2][264];   // P(256)+Q(8) per (dest,parity)

    for (int u = t; u < SDIM * KH; u += 128) sw1[u] = kn_w1[u];
    if (t < KH) sb1[t] = kn_b1[t];
    {
        const float4* xs = (const float4*)(X + (size_t)b * NN * FIN);
        for (int u = t; u < NN * FIN / 4; u += 128) ((float4*)sxb)[u] = xs[u];
    }

    // parity-0 warp of each dest compacts row A[b,n,:] (contiguous)
    if (pr == 0) {
        const float4* Ar = (const float4*)(A + ((size_t)b * NN + n) * NN);
        float4 av = Ar[lane];                           // i = 4*lane .. +3
        int cnt = 0;
#pragma unroll
        for (int e = 0; e < 4; ++e) {
            float v = (e == 0) ? av.x : (e == 1) ? av.y : (e == 2) ? av.z : av.w;
            unsigned m = __ballot_sync(0xffffffffu, v != 0.f);
            if (v != 0.f) {
                int pos = cnt + __popc(m & ((1u << lane) - 1u));
                if (pos < CAP) { sa[d][pos] = v; sn[d][pos] = (short)(4 * lane + e); }
            }
            cnt += __popc(m);
        }
        if (lane == 0) scnt[d] = (cnt > CAP) ? CAP : cnt;
    }
    __syncthreads();

    int cnt = scnt[d];
    float P[8] = {0.f, 0.f, 0.f, 0.f, 0.f, 0.f, 0.f, 0.f};
    float q[8] = {0.f, 0.f, 0.f, 0.f, 0.f, 0.f, 0.f, 0.f};
    const float* Erow = E + ((size_t)b * NN + n) * NN * SDIM;

    int j = pr;
    if (j < cnt) {
        int   i = sn[d][j];
        float a = sa[d][j];
        const float4* e4 = (const float4*)(Erow + (size_t)i * SDIM);
        float4 e0 = e4[0], e1 = e4[1];

        while (j < cnt) {
            int jn = j + 2;
            int inext = 0; float anext = 0.f;
            float4 p0 = e0, p1 = e1;
            if (jn < cnt) {
                inext = sn[d][jn]; anext = sa[d][jn];
                const float4* pe = (const float4*)(Erow + (size_t)inext * SDIM);
                p0 = pe[0]; p1 = pe[1];
            }

            // h_k for k = lane: two 4-FMA chains then add
            float h0 = sb1[lane];
            h0 = fmaf(e0.x, sw1[0 * KH + lane], h0);
            h0 = fmaf(e0.y, sw1[1 * KH + lane], h0);
            h0 = fmaf(e0.z, sw1[2 * KH + lane], h0);
            h0 = fmaf(e0.w, sw1[3 * KH + lane], h0);
            float h1 = 0.f;
            h1 = fmaf(e1.x, sw1[4 * KH + lane], h1);
            h1 = fmaf(e1.y, sw1[5 * KH + lane], h1);
            h1 = fmaf(e1.z, sw1[6 * KH + lane], h1);
            h1 = fmaf(e1.w, sw1[7 * KH + lane], h1);
            float hv = fmaxf(h0 + h1, 0.f);
            float ah = a * hv;

            const float4* xp = (const float4*)(sxb + i * FIN);  // broadcast LDS
            float4 x0 = xp[0], x1 = xp[1];
            P[0] = fmaf(ah, x0.x, P[0]);  P[1] = fmaf(ah, x0.y, P[1]);
            P[2] = fmaf(ah, x0.z, P[2]);  P[3] = fmaf(ah, x0.w, P[3]);
            P[4] = fmaf(ah, x1.x, P[4]);  P[5] = fmaf(ah, x1.y, P[5]);
            P[6] = fmaf(ah, x1.z, P[6]);  P[7] = fmaf(ah, x1.w, P[7]);
            q[0] = fmaf(a, x0.x, q[0]);   q[1] = fmaf(a, x0.y, q[1]);
            q[2] = fmaf(a, x0.z, q[2]);   q[3] = fmaf(a, x0.w, q[3]);
            q[4] = fmaf(a, x1.x, q[4]);   q[5] = fmaf(a, x1.y, q[5]);
            q[6] = fmaf(a, x1.z, q[6]);   q[7] = fmaf(a, x1.w, q[7]);

            j = jn; i = inext; a = anext; e0 = p0; e1 = p1;
        }
    }

    // stage per-parity partials. sP[d][pr] base = (2d+pr)*264 floats = 1056B,
    // 16B-aligned given alignas(16) on sP.
    {
        float* dst = sP[d][pr];
        ((float4*)(dst + lane * 8))[0] = make_float4(P[0], P[1], P[2], P[3]);
        ((float4*)(dst + lane * 8))[1] = make_float4(P[4], P[5], P[6], P[7]);
        if (lane == 0) {
#pragma unroll
            for (int f = 0; f < 8; ++f) dst[256 + f] = q[f];
        }
    }
    __syncthreads();

    // merge parities and write V row (warps 0,1 -> dests 0,1)
    if (w < 2) {
        int d2 = w, n2 = n0 + d2;
        float* vrow = g_V + ((size_t)b * NN + n2) * VROW;
        const float* pA = sP[d2][0];
        const float* pB = sP[d2][1];
        float4 a0 = ((const float4*)(pA + lane * 8))[0];
        float4 a1 = ((const float4*)(pA + lane * 8))[1];
        float4 b0 = ((const float4*)(pB + lane * 8))[0];
        float4 b1 = ((const float4*)(pB + lane * 8))[1];
        a0.x += b0.x; a0.y += b0.y; a0.z += b0.z; a0.w += b0.w;
        a1.x += b1.x; a1.y += b1.y; a1.z += b1.z; a1.w += b1.w;
        ((float4*)(vrow + lane * 8))[0] = a0;
        ((float4*)(vrow + lane * 8))[1] = a1;
        if (lane < 8) {
            vrow[256 + lane] = pA[256 + lane] + pB[256 + lane];   // Q
            vrow[264 + lane] = sxb[n2 * FIN + lane];              // x
        }
    }
}

// ---------------------------------------------------------------------------
// k_gemm: grid 512 (b x 32 groups of 4 dests), block 256.
// Thread (og = t&15 -> o-quad, jq = t>>4 -> 17-row j slice) holds its W slice
// (17 x float4) in registers, loops 4 destinations. Fuses conv_b + ReLU + pool.
// ---------------------------------------------------------------------------
__global__ void __launch_bounds__(256)
k_gemm(const float* __restrict__ kn_w2,
       const float* __restrict__ kn_b2,
       const float* __restrict__ root_w,
       const float* __restrict__ conv_b) {
    int t    = threadIdx.x;
    int w    = t >> 5;             // warp 0..7
    int lane = t & 31;
    int og   = t & 15;             // o = og*4 .. +4
    int jbase = (t >> 4) * 17;     // j slice [jbase, jbase+17)
    int b    = blockIdx.x >> 5;
    int n0   = (blockIdx.x & 31) * 4;

    __shared__ alignas(16) float sV    [4][VROW];   // 4.5KB
    __shared__ alignas(16) float s_part[8][FO];     // 2KB

    // warps w and w+4 each load half of dest (w&3)'s V row (68 float4 total)
    {
        int dd = w & 3, hf = w >> 2;
        const float4* src = (const float4*)(g_V + ((size_t)b * NN + n0 + dd) * VROW);
        for (int u = lane + 32 * hf; u < 68; u += 64) ((float4*)sV[dd])[u] = src[u];
    }

    // W slice into registers: rows j = jbase..jbase+16, columns og*4..+4
    float4 Wr[17];
#pragma unroll
    for (int jj = 0; jj < 17; ++jj) {
        int jg = jbase + jj;
        const float* src;
        if (jg < 256)      src = kn_w2  + jg * 64;
        else if (jg < 264) src = kn_b2  + (jg - 256) * 64;
        else               src = root_w + (jg - 264) * 64;
        Wr[jj] = ((const float4*)src)[og];
    }
    __syncthreads();

    float cb = (t < FO) ? conv_b[t] : 0.f;
    float pool = 0.f;

    for (int dd = 0; dd < 4; ++dd) {
        float4 acc = make_float4(0.f, 0.f, 0.f, 0.f);
        const float* V = sV[dd] + jbase;
#pragma unroll
        for (int jj = 0; jj < 17; ++jj) {
            float vj = V[jj];
            acc.x = fmaf(Wr[jj].x, vj, acc.x);
            acc.y = fmaf(Wr[jj].y, vj, acc.y);
            acc.z = fmaf(Wr[jj].z, vj, acc.z);
            acc.w = fmaf(Wr[jj].w, vj, acc.w);
        }
        acc.x += __shfl_xor_sync(0xffffffffu, acc.x, 16);
        acc.y += __shfl_xor_sync(0xffffffffu, acc.y, 16);
        acc.z += __shfl_xor_sync(0xffffffffu, acc.z, 16);
        acc.w += __shfl_xor_sync(0xffffffffu, acc.w, 16);
        if (lane < 16) ((float4*)s_part[w])[og] = acc;
        __syncthreads();
        if (t < FO) {
            float s = 0.f;
#pragma unroll
            for (int ww = 0; ww < 8; ++ww) s += s_part[ww][t];
            pool += fmaxf(s + cb, 0.f);
        }
        __syncthreads();
    }

    if (t < FO) atomicAdd(&g_pool[b * FO + t], pool);
}

// ---------------------------------------------------------------------------
// k_head: grid B, 64 threads. Read g_pool (restore zero), /N, Dense(32,relu),
// Dense(1,sigmoid).
// ---------------------------------------------------------------------------
__global__ void k_head(const float* __restrict__ fc_w,
                       const float* __restrict__ fc_b,
                       const float* __restrict__ out_w,
                       const float* __restrict__ out_b,
                       float* __restrict__ out) {
    int b = blockIdx.x;
    int t = threadIdx.x;
    __shared__ float sfeat[FO];

    float v = g_pool[b * FO + t];
    g_pool[b * FO + t] = 0.f;          // restore zero for next call/replay
    sfeat[t] = v * (1.f / NN);
    __syncthreads();

    if (t < 32) {
        float f = fc_b[t];
#pragma unroll
        for (int o2 = 0; o2 < FO; ++o2) f = fmaf(sfeat[o2], fc_w[o2 * 32 + t], f);
        f = fmaxf(f, 0.f);
        float p = f * out_w[t];
#pragma unroll
        for (int off = 16; off > 0; off >>= 1)
            p += __shfl_xor_sync(0xffffffffu, p, off);
        if (t == 0) out[b] = 1.f / (1.f + expf(-(p + out_b[0])));
    }
}

// ---------------------------------------------------------------------------
// Inputs (metadata order): A, X, E, kn_w1, kn_b1, kn_w2, kn_b2, root_w, conv_b,
//                          fc_w, fc_b, out_w, out_b
// ---------------------------------------------------------------------------
extern "C" void kernel_launch(void* const* d_in, const int* in_sizes, int n_in,
                              void* d_out, int out_size) {
    const float* A      = (const float*)d_in[0];
    const float* X      = (const float*)d_in[1];
    const float* E      = (const float*)d_in[2];
    const float* kn_w1  = (const float*)d_in[3];
    const float* kn_b1  = (const float*)d_in[4];
    const float* kn_w2  = (const float*)d_in[5];
    const float* kn_b2  = (const float*)d_in[6];
    const float* root_w = (const float*)d_in[7];
    const float* conv_b = (const float*)d_in[8];
    const float* fc_w   = (const float*)d_in[9];
    const float* fc_b   = (const float*)d_in[10];
    const float* out_w  = (const float*)d_in[11];
    const float* out_b  = (const float*)d_in[12];
    float* out = (float*)d_out;

    k_build<<<1024, 128>>>(A, X, E, kn_w1, kn_b1);
    k_gemm <<<512, 256>>>(kn_w2, kn_b2, root_w, conv_b);
    k_head <<<BB, 64>>>(fc_w, fc_b, out_w, out_b, out);
}